// round 1
// baseline (speedup 1.0000x reference)
#include <cuda_runtime.h>
#include <math_constants.h>

// KNN min-dist over 9x9 window, C=3, zero-padded, direct (t-o)^2 form.
// Fixed shapes: B=4, C=3, H=256, W=512.

#define BDIM 128
#define TW 32          // tile width (pixels)  -> 32 threads in x
#define TH 16          // tile height (pixels) -> 4 thread rows * TY
#define TY 4           // pixels per thread (vertical)
#define HALO 4
#define SW 9
#define SH_W (TW + 2*HALO)   // 40
#define SH_H (TH + 2*HALO)   // 24

#define B_ 4
#define H_ 256
#define W_ 512
#define HW_ (H_*W_)

__global__ __launch_bounds__(BDIM) void knn_min_kernel(
    const float* __restrict__ tfm, const float* __restrict__ obs,
    float* __restrict__ out)
{
    __shared__ float s[3][SH_H][SH_W];

    const int b  = blockIdx.z;
    const int x0 = blockIdx.x * TW;
    const int y0 = blockIdx.y * TH;
    const int tid = threadIdx.x;
    const int tx = tid & 31;
    const int ty = tid >> 5;

    const float* obs_b = obs + b * 3 * HW_;
    const float* tfm_b = tfm + b * 3 * HW_;

    // ---- load obs tile (3 channel planes) with zero-padded halo ----
    for (int idx = tid; idx < SH_H * SH_W; idx += BDIM) {
        int iy = idx / SH_W;
        int ix = idx - iy * SH_W;
        int gy = y0 - HALO + iy;
        int gx = x0 - HALO + ix;
        bool ok = (gy >= 0) & (gy < H_) & (gx >= 0) & (gx < W_);
        int g = gy * W_ + gx;
        float v0 = 0.f, v1 = 0.f, v2 = 0.f;
        if (ok) {
            v0 = obs_b[g];
            v1 = obs_b[HW_ + g];
            v2 = obs_b[2 * HW_ + g];
        }
        s[0][iy][ix] = v0;
        s[1][iy][ix] = v1;
        s[2][iy][ix] = v2;
    }
    __syncthreads();

    // ---- tfm pixels for this thread (TY vertical pixels) ----
    const int ybase = y0 + ty * TY;
    const int x = x0 + tx;
    float t0[TY], t1[TY], t2[TY];
#pragma unroll
    for (int k = 0; k < TY; k++) {
        int g = (ybase + k) * W_ + x;
        t0[k] = tfm_b[g];
        t1[k] = tfm_b[HW_ + g];
        t2[k] = tfm_b[2 * HW_ + g];
    }

    float m[TY];
#pragma unroll
    for (int k = 0; k < TY; k++) m[k] = CUDART_INF_F;

    const int rbase = ty * TY;  // smem row of (pixel k=0, di=0)

#pragma unroll 1
    for (int dj = 0; dj < SW; dj++) {
        // Load the 12 rows needed for this dj column, all 3 channels.
        float o0[TY + 8], o1[TY + 8], o2[TY + 8];
#pragma unroll
        for (int r = 0; r < TY + 8; r++) {
            o0[r] = s[0][rbase + r][tx + dj];
            o1[r] = s[1][rbase + r][tx + dj];
            o2[r] = s[2][rbase + r][tx + dj];
        }
#pragma unroll
        for (int k = 0; k < TY; k++) {
#pragma unroll
            for (int di = 0; di < SW; di++) {
                float d0 = t0[k] - o0[k + di];
                float d1 = t1[k] - o1[k + di];
                float d2 = t2[k] - o2[k + di];
                float d = fmaf(d2, d2, fmaf(d1, d1, d0 * d0));
                m[k] = fminf(m[k], d);
            }
        }
    }

    float* out_b = out + b * HW_;
#pragma unroll
    for (int k = 0; k < TY; k++) {
        out_b[(ybase + k) * W_ + x] = sqrtf(m[k]);
    }
}

extern "C" void kernel_launch(void* const* d_in, const int* in_sizes, int n_in,
                              void* d_out, int out_size)
{
    const float* tfm = (const float*)d_in[0];
    const float* obs = (const float*)d_in[1];
    float* out = (float*)d_out;
    (void)in_sizes; (void)n_in; (void)out_size;

    dim3 grid(W_ / TW, H_ / TH, B_);
    dim3 block(BDIM);
    knn_min_kernel<<<grid, block>>>(tfm, obs, out);
}